// round 2
// baseline (speedup 1.0000x reference)
#include <cuda_runtime.h>
#include <math.h>

#define NB 4
#define NPT 4096
#define NF 256
#define NTOT (NB*NPT)
#define DS 80

__device__ unsigned char g_adj[(size_t)NTOT * NPT];
__device__ float g_sq[NTOT];
__device__ int g_p[NTOT], g_q[NTOT], g_root[NTOT], g_labval[NTOT];
__device__ int g_ptrA[NTOT], g_ptrB[NTOT], g_v[NTOT], g_labels[NTOT];
__device__ int g_hist[NB][NTOT + 1];
__device__ int g_map[NB][NTOT + 1];
__device__ int g_members[NTOT];
__device__ int g_clusM[NTOT], g_clusB[NTOT], g_clusBase[NTOT], g_cursor[NTOT];
__device__ int g_Kb[NB], g_KbBase[NB], g_Ktot, g_Rtot;
__device__ int g_gidx[(size_t)NTOT * DS];

// ---- 1: row sums of squares (+ zero output) ----
__global__ void k_sq(const float* __restrict__ feat, float* __restrict__ out) {
    int gt = blockIdx.x * blockDim.x + threadIdx.x;
    if (gt == 0) out[0] = 0.f;
    int w = gt >> 5, lane = gt & 31;
    const float* r = feat + (size_t)w * NF;
    float s = 0.f;
#pragma unroll
    for (int t = 0; t < NF / 32; t++) { float x = r[t * 32 + lane]; s = fmaf(x, x, s); }
#pragma unroll
    for (int o = 16; o; o >>= 1) s += __shfl_xor_sync(0xffffffffu, s, o);
    if (lane == 0) g_sq[w] = s;
}

// ---- 2: symmetric SGEMM tile -> adjacency bytes ----
__global__ __launch_bounds__(256) void k_gemm(const float* __restrict__ feat) {
    int bi = blockIdx.y, bj = blockIdx.x, b = blockIdx.z;
    if (bj < bi) return;
    __shared__ float As[32][128];
    __shared__ float Bs[32][128];
    int tid = threadIdx.x, tx = tid & 15, ty = tid >> 4;
    const float* A = feat + (size_t)b * NPT * NF;
    int iBase = bi * 128, jBase = bj * 128;
    float acc[8][8];
#pragma unroll
    for (int y = 0; y < 8; y++)
#pragma unroll
        for (int x = 0; x < 8; x++) acc[y][x] = 0.f;
    for (int kt = 0; kt < NF; kt += 32) {
#pragma unroll
        for (int li = 0; li < 4; li++) {
            int lin = tid + li * 256, row = lin >> 3, kc = (lin & 7) * 4;
            float4 va = *(const float4*)(A + (size_t)(iBase + row) * NF + kt + kc);
            As[kc][row] = va.x; As[kc + 1][row] = va.y; As[kc + 2][row] = va.z; As[kc + 3][row] = va.w;
            float4 vb = *(const float4*)(A + (size_t)(jBase + row) * NF + kt + kc);
            Bs[kc][row] = vb.x; Bs[kc + 1][row] = vb.y; Bs[kc + 2][row] = vb.z; Bs[kc + 3][row] = vb.w;
        }
        __syncthreads();
#pragma unroll
        for (int k = 0; k < 32; k++) {
            float a[8], bb[8];
            *(float4*)(a) = *(const float4*)(&As[k][ty * 8]);
            *(float4*)(a + 4) = *(const float4*)(&As[k][ty * 8 + 4]);
            *(float4*)(bb) = *(const float4*)(&Bs[k][tx * 8]);
            *(float4*)(bb + 4) = *(const float4*)(&Bs[k][tx * 8 + 4]);
#pragma unroll
            for (int y = 0; y < 8; y++)
#pragma unroll
                for (int x = 0; x < 8; x++) acc[y][x] = fmaf(a[y], bb[x], acc[y][x]);
        }
        __syncthreads();
    }
    float sqi[8], sqj[8];
#pragma unroll
    for (int y = 0; y < 8; y++) sqi[y] = g_sq[b * NPT + iBase + ty * 8 + y];
#pragma unroll
    for (int x = 0; x < 8; x++) sqj[x] = g_sq[b * NPT + jBase + tx * 8 + x];
    unsigned char av[64];
#pragma unroll
    for (int y = 0; y < 8; y++)
#pragma unroll
        for (int x = 0; x < 8; x++) {
            float d2 = sqi[y] + sqj[x] - 2.f * acc[y][x];
            av[y * 8 + x] = (sqrtf(fmaxf(d2, 0.f)) < 22.63f) ? 1 : 0;
        }
    unsigned char* sb = (unsigned char*)&As[0][0];
#pragma unroll
    for (int y = 0; y < 8; y++)
#pragma unroll
        for (int x = 0; x < 8; x++) sb[(ty * 8 + y) * 128 + tx * 8 + x] = av[y * 8 + x];
    __syncthreads();
    {
        unsigned char* dst = g_adj + ((size_t)(b * NPT + iBase)) * NPT + jBase;
#pragma unroll
        for (int li = 0; li < 4; li++) {
            int lin = tid + li * 256, row = lin >> 3, c = (lin & 7) * 16;
            *(uint4*)(dst + (size_t)row * NPT + c) = *(const uint4*)(sb + row * 128 + c);
        }
    }
    if (bi != bj) {
        __syncthreads();
#pragma unroll
        for (int y = 0; y < 8; y++)
#pragma unroll
            for (int x = 0; x < 8; x++) sb[(tx * 8 + x) * 128 + ty * 8 + y] = av[y * 8 + x];
        __syncthreads();
        unsigned char* dst = g_adj + ((size_t)(b * NPT + jBase)) * NPT + iBase;
#pragma unroll
        for (int li = 0; li < 4; li++) {
            int lin = tid + li * 256, row = lin >> 3, c = (lin & 7) * 16;
            *(uint4*)(dst + (size_t)row * NPT + c) = *(const uint4*)(sb + row * 128 + c);
        }
    }
}

// ---- 3: per-row p (last neighbor < j) and q (last neighbor) ----
__global__ void k_rowpq() {
    int gw = (blockIdx.x * blockDim.x + threadIdx.x) >> 5;
    int lane = threadIdx.x & 31;
    int j = gw & (NPT - 1);
    const uint4* row = (const uint4*)(g_adj + (size_t)gw * NPT);
    int pmax = -1, qmax = -1;
#pragma unroll
    for (int tI = 0; tI < 8; tI++) {
        uint4 v = row[tI * 32 + lane];
        int base = (tI * 32 + lane) * 16;
        unsigned int ws[4] = {v.x, v.y, v.z, v.w};
#pragma unroll
        for (int w = 0; w < 4; w++) {
            unsigned int word = ws[w];
            if (!word) continue;
#pragma unroll
            for (int bb = 0; bb < 4; bb++)
                if ((word >> (8 * bb)) & 0xFFu) {
                    int idx = base + w * 4 + bb;
                    qmax = max(qmax, idx);
                    if (idx < j) pmax = max(pmax, idx);
                }
        }
    }
#pragma unroll
    for (int o = 16; o; o >>= 1) {
        qmax = max(qmax, __shfl_xor_sync(0xffffffffu, qmax, o));
        pmax = max(pmax, __shfl_xor_sync(0xffffffffu, pmax, o));
    }
    if (lane == 0) { g_p[gw] = pmax; g_q[gw] = qmax; g_root[gw] = (pmax < 0); }
}

// ---- 4: root label scan + pointer jumping + final labels ----
__global__ __launch_bounds__(1024) void k_label() {
    __shared__ int sc[1024];
    int t = threadIdx.x, base = t * 16, cnt = 0;
#pragma unroll
    for (int e = 0; e < 16; e++) cnt += g_root[base + e];
    sc[t] = cnt;
    __syncthreads();
    for (int off = 1; off < 1024; off <<= 1) {
        int v = (t >= off) ? sc[t - off] : 0;
        __syncthreads();
        sc[t] += v;
        __syncthreads();
    }
    int run = sc[t] - cnt;
#pragma unroll
    for (int e = 0; e < 16; e++) {
        int x = base + e;
        if (g_root[x]) { g_labval[x] = 1 + run; run++; g_ptrA[x] = x; }
        else { g_labval[x] = 0; g_ptrA[x] = (x & ~(NPT - 1)) + g_p[x]; }
    }
    if (t == 1023) g_Rtot = sc[1023];
    __syncthreads();
    for (int it = 0; it < 12; it++) {
        if (!(it & 1)) { for (int e = 0; e < 16; e++) { int x = base + e; g_ptrB[x] = g_ptrA[g_ptrA[x]]; } }
        else           { for (int e = 0; e < 16; e++) { int x = base + e; g_ptrA[x] = g_ptrB[g_ptrB[x]]; } }
        __syncthreads();
    }
#pragma unroll
    for (int e = 0; e < 16; e++) { int x = base + e; g_v[x] = g_labval[g_ptrA[x]]; }
    __syncthreads();
#pragma unroll
    for (int e = 0; e < 16; e++) { int x = base + e; g_labels[x] = g_v[(x & ~(NPT - 1)) + g_q[x]]; }
}

// ---- 5: histogram / unique / ordered member lists ----
__global__ __launch_bounds__(1024) void k_build() {
    int t = threadIdx.x;
    for (int i = t; i < NB * (NTOT + 1); i += 1024) (&g_hist[0][0])[i] = 0;
    __syncthreads();
#pragma unroll
    for (int e = 0; e < 16; e++) {
        int x = t * 16 + e;
        atomicAdd(&g_hist[x >> 12][g_labels[x]], 1);
    }
    __syncthreads();
    int R = g_Rtot;
    if (t < NB) {
        int k = 0;
        for (int l = 1; l <= R; l++) if (g_hist[t][l] > 0) { g_map[t][l] = k; k++; }
        g_Kb[t] = k;
    }
    __syncthreads();
    if (t == 0) {
        int s = 0;
        for (int b = 0; b < NB; b++) { g_KbBase[b] = s; s += g_Kb[b]; }
        g_Ktot = s;
    }
    __syncthreads();
    if (t < NB) {
        int b = t, off = 0, k = 0;
        for (int l = 1; l <= R; l++) {
            int c = g_hist[b][l];
            if (c > 0) {
                int slot = g_KbBase[b] + k;
                g_clusM[slot] = c; g_clusB[slot] = b;
                g_clusBase[slot] = b * NPT + off; g_cursor[slot] = b * NPT + off;
                off += c; k++;
            }
        }
        for (int jj = 0; jj < NPT; jj++) {
            int l = g_labels[b * NPT + jj];
            g_members[g_cursor[g_KbBase[b] + g_map[b][l]]++] = jj;
        }
    }
}

// ---- 6: numpy RandomState(0).choice replay (MT19937, legacy 32-bit masked rejection) ----
__global__ void k_rng() {
    unsigned int key[624];
    unsigned int s = 0u;
    for (int i = 0; i < 624; i++) { key[i] = s; s = 1812433253u * (s ^ (s >> 30)) + (unsigned)i + 1u; }
    int pos = 624;
    int K = g_Ktot;
    for (int slot = 0; slot < K; slot++) {
        int M = g_clusM[slot], b = g_clusB[slot], base = g_clusBase[slot];
        if (M <= 1) {
            int gj = b * NPT + g_members[base];
            for (int tt = 0; tt < DS; tt++) g_gidx[slot * DS + tt] = gj;
        } else {
            unsigned int rng = (unsigned int)(M - 1), mask = rng;
            mask |= mask >> 1; mask |= mask >> 2; mask |= mask >> 4; mask |= mask >> 8; mask |= mask >> 16;
            for (int tt = 0; tt < DS; tt++) {
                unsigned int r;
                do {
                    if (pos == 624) {
                        for (int i = 0; i < 624; i++) {
                            unsigned int y = (key[i] & 0x80000000u) | (key[(i + 1) % 624] & 0x7fffffffu);
                            unsigned int v = key[(i + 397) % 624] ^ (y >> 1);
                            key[i] = (y & 1u) ? (v ^ 0x9908b0dfu) : v;
                        }
                        pos = 0;
                    }
                    unsigned int y = key[pos++];
                    y ^= y >> 11; y ^= (y << 7) & 0x9d2c5680u; y ^= (y << 15) & 0xefc60000u; y ^= y >> 18;
                    r = y & mask;
                } while (r > rng);
                g_gidx[slot * DS + tt] = b * NPT + g_members[base + (int)r];
            }
        }
    }
}

// ---- 7: PointNet-lite classifier + BCE ----
__global__ __launch_bounds__(128) void k_classify(const float* __restrict__ pts,
        const float* __restrict__ W1, const float* __restrict__ b1,
        const float* __restrict__ W2, const float* __restrict__ b2,
        const float* __restrict__ W3, const float* __restrict__ b3,
        float* __restrict__ out) {
    __shared__ float sW1[192], sb1[64], sW3[256], sb3[2];
    __shared__ float sp[240];
    __shared__ float sh1[80 * 64];
    __shared__ float sred[128];
    int t = threadIdx.x;
    for (int i = t; i < 192; i += 128) sW1[i] = W1[i];
    if (t < 64) sb1[t] = b1[t];
    for (int i = t; i < 256; i += 128) sW3[i] = W3[i];
    if (t < 2) sb3[t] = b3[t];
    float rW2[64];
#pragma unroll
    for (int k = 0; k < 64; k++) rW2[k] = W2[k * 128 + t];
    float rb2 = b2[t];
    __syncthreads();
    int K = g_Ktot;
    for (int slot = blockIdx.x; slot < K; slot += gridDim.x) {
        for (int i = t; i < 240; i += 128) {
            int pt = i / 3, f = i - pt * 3;
            sp[i] = pts[(size_t)g_gidx[slot * DS + pt] * 3 + f];
        }
        __syncthreads();
        for (int o = t; o < 80 * 64; o += 128) {
            int pt = o >> 6, c = o & 63;
            float a = sb1[c] + sp[pt * 3] * sW1[c] + sp[pt * 3 + 1] * sW1[64 + c] + sp[pt * 3 + 2] * sW1[128 + c];
            sh1[o] = fmaxf(a, 0.f);
        }
        __syncthreads();
        float m = -3.402823466e38f;
        for (int pt = 0; pt < 80; pt++) {
            const float* h = &sh1[pt * 64];
            float a = rb2;
#pragma unroll
            for (int k = 0; k < 64; k++) a = fmaf(h[k], rW2[k], a);
            m = fmaxf(m, a);
        }
        float gt = fmaxf(m, 0.f);
        sred[t] = gt * sW3[2 * t];
        __syncthreads();
        for (int off = 64; off; off >>= 1) { if (t < off) sred[t] += sred[t + off]; __syncthreads(); }
        float l0 = sred[0] + sb3[0];
        __syncthreads();
        sred[t] = gt * sW3[2 * t + 1];
        __syncthreads();
        for (int off = 64; off; off >>= 1) { if (t < off) sred[t] += sred[t + off]; __syncthreads(); }
        if (t == 0) {
            float l1 = sred[0] + sb3[1];
            float loss = fminf(log1pf(expf(l0 - l1)), 100.f);
            atomicAdd(out, loss / (float)g_Kb[g_clusB[slot]]);
        }
        __syncthreads();
    }
}

extern "C" void kernel_launch(void* const* d_in, const int* in_sizes, int n_in,
                              void* d_out, int out_size) {
    const float* feat = (const float*)d_in[0];
    const float* pts  = (const float*)d_in[1];
    const float* W1 = (const float*)d_in[2];
    const float* b1 = (const float*)d_in[3];
    const float* W2 = (const float*)d_in[4];
    const float* b2 = (const float*)d_in[5];
    const float* W3 = (const float*)d_in[6];
    const float* b3 = (const float*)d_in[7];
    float* out = (float*)d_out;
    k_sq<<<NTOT * 32 / 256, 256>>>(feat, out);
    k_gemm<<<dim3(NPT / 128, NPT / 128, NB), 256>>>(feat);
    k_rowpq<<<NTOT * 32 / 256, 256>>>();
    k_label<<<1, 1024>>>();
    k_build<<<1, 1024>>>();
    k_rng<<<1, 1>>>();
    k_classify<<<32, 128>>>(pts, W1, b1, W2, b2, W3, b3, out);
}

// round 3
// speedup vs baseline: 1.6245x; 1.6245x over previous
#include <cuda_runtime.h>
#include <math.h>

#define NB 4
#define NPT 4096
#define NF 256
#define NTOT (NB*NPT)
#define DS 80

__device__ unsigned char g_adj[(size_t)NTOT * NPT];
__device__ float g_sq[NTOT];
__device__ int g_p[NTOT], g_q[NTOT], g_root[NTOT], g_labval[NTOT];
__device__ int g_ptrA[NTOT], g_ptrB[NTOT], g_v[NTOT], g_labels[NTOT];
__device__ int g_hist[NB][NTOT + 1];
__device__ int g_map[NB][NTOT + 1];
__device__ int g_members[NTOT];
__device__ int g_clusM[NTOT], g_clusB[NTOT], g_clusBase[NTOT], g_clusL[NTOT];
__device__ int g_Kb[NB], g_KbBase[NB], g_Ktot, g_Rtot;
__device__ int g_gidx[(size_t)NTOT * DS];

// ---- 1: row sums of squares (+ zero output) ----
__global__ void k_sq(const float* __restrict__ feat, float* __restrict__ out) {
    int gt = blockIdx.x * blockDim.x + threadIdx.x;
    if (gt == 0) out[0] = 0.f;
    int w = gt >> 5, lane = gt & 31;
    const float* r = feat + (size_t)w * NF;
    float s = 0.f;
#pragma unroll
    for (int t = 0; t < NF / 32; t++) { float x = r[t * 32 + lane]; s = fmaf(x, x, s); }
#pragma unroll
    for (int o = 16; o; o >>= 1) s += __shfl_xor_sync(0xffffffffu, s, o);
    if (lane == 0) g_sq[w] = s;
}

// ---- 2: symmetric SGEMM tile -> adjacency bytes ----
__global__ __launch_bounds__(256) void k_gemm(const float* __restrict__ feat) {
    int bi = blockIdx.y, bj = blockIdx.x, b = blockIdx.z;
    if (bj < bi) return;
    __shared__ float As[32][128];
    __shared__ float Bs[32][128];
    int tid = threadIdx.x, tx = tid & 15, ty = tid >> 4;
    const float* A = feat + (size_t)b * NPT * NF;
    int iBase = bi * 128, jBase = bj * 128;
    float acc[8][8];
#pragma unroll
    for (int y = 0; y < 8; y++)
#pragma unroll
        for (int x = 0; x < 8; x++) acc[y][x] = 0.f;
    for (int kt = 0; kt < NF; kt += 32) {
#pragma unroll
        for (int li = 0; li < 4; li++) {
            int lin = tid + li * 256, row = lin >> 3, kc = (lin & 7) * 4;
            float4 va = *(const float4*)(A + (size_t)(iBase + row) * NF + kt + kc);
            As[kc][row] = va.x; As[kc + 1][row] = va.y; As[kc + 2][row] = va.z; As[kc + 3][row] = va.w;
            float4 vb = *(const float4*)(A + (size_t)(jBase + row) * NF + kt + kc);
            Bs[kc][row] = vb.x; Bs[kc + 1][row] = vb.y; Bs[kc + 2][row] = vb.z; Bs[kc + 3][row] = vb.w;
        }
        __syncthreads();
#pragma unroll
        for (int k = 0; k < 32; k++) {
            float a[8], bb[8];
            *(float4*)(a) = *(const float4*)(&As[k][ty * 8]);
            *(float4*)(a + 4) = *(const float4*)(&As[k][ty * 8 + 4]);
            *(float4*)(bb) = *(const float4*)(&Bs[k][tx * 8]);
            *(float4*)(bb + 4) = *(const float4*)(&Bs[k][tx * 8 + 4]);
#pragma unroll
            for (int y = 0; y < 8; y++)
#pragma unroll
                for (int x = 0; x < 8; x++) acc[y][x] = fmaf(a[y], bb[x], acc[y][x]);
        }
        __syncthreads();
    }
    float sqi[8], sqj[8];
#pragma unroll
    for (int y = 0; y < 8; y++) sqi[y] = g_sq[b * NPT + iBase + ty * 8 + y];
#pragma unroll
    for (int x = 0; x < 8; x++) sqj[x] = g_sq[b * NPT + jBase + tx * 8 + x];
    unsigned char av[64];
#pragma unroll
    for (int y = 0; y < 8; y++)
#pragma unroll
        for (int x = 0; x < 8; x++) {
            float d2 = sqi[y] + sqj[x] - 2.f * acc[y][x];
            av[y * 8 + x] = (sqrtf(fmaxf(d2, 0.f)) < 22.63f) ? 1 : 0;
        }
    unsigned char* sb = (unsigned char*)&As[0][0];
#pragma unroll
    for (int y = 0; y < 8; y++)
#pragma unroll
        for (int x = 0; x < 8; x++) sb[(ty * 8 + y) * 128 + tx * 8 + x] = av[y * 8 + x];
    __syncthreads();
    {
        unsigned char* dst = g_adj + ((size_t)(b * NPT + iBase)) * NPT + jBase;
#pragma unroll
        for (int li = 0; li < 4; li++) {
            int lin = tid + li * 256, row = lin >> 3, c = (lin & 7) * 16;
            *(uint4*)(dst + (size_t)row * NPT + c) = *(const uint4*)(sb + row * 128 + c);
        }
    }
    if (bi != bj) {
        __syncthreads();
#pragma unroll
        for (int y = 0; y < 8; y++)
#pragma unroll
            for (int x = 0; x < 8; x++) sb[(tx * 8 + x) * 128 + ty * 8 + y] = av[y * 8 + x];
        __syncthreads();
        unsigned char* dst = g_adj + ((size_t)(b * NPT + jBase)) * NPT + iBase;
#pragma unroll
        for (int li = 0; li < 4; li++) {
            int lin = tid + li * 256, row = lin >> 3, c = (lin & 7) * 16;
            *(uint4*)(dst + (size_t)row * NPT + c) = *(const uint4*)(sb + row * 128 + c);
        }
    }
}

// ---- 3: per-row p (last neighbor < j) and q (last neighbor) ----
__global__ void k_rowpq() {
    int gw = (blockIdx.x * blockDim.x + threadIdx.x) >> 5;
    int lane = threadIdx.x & 31;
    int j = gw & (NPT - 1);
    const uint4* row = (const uint4*)(g_adj + (size_t)gw * NPT);
    int pmax = -1, qmax = -1;
#pragma unroll
    for (int tI = 0; tI < 8; tI++) {
        uint4 v = row[tI * 32 + lane];
        int base = (tI * 32 + lane) * 16;
        unsigned int ws[4] = {v.x, v.y, v.z, v.w};
#pragma unroll
        for (int w = 0; w < 4; w++) {
            unsigned int word = ws[w];
            if (!word) continue;
#pragma unroll
            for (int bb = 0; bb < 4; bb++)
                if ((word >> (8 * bb)) & 0xFFu) {
                    int idx = base + w * 4 + bb;
                    qmax = max(qmax, idx);
                    if (idx < j) pmax = max(pmax, idx);
                }
        }
    }
#pragma unroll
    for (int o = 16; o; o >>= 1) {
        qmax = max(qmax, __shfl_xor_sync(0xffffffffu, qmax, o));
        pmax = max(pmax, __shfl_xor_sync(0xffffffffu, pmax, o));
    }
    if (lane == 0) { g_p[gw] = pmax; g_q[gw] = qmax; g_root[gw] = (pmax < 0); }
}

// ---- 4a: root label scan + pointer init (single block, short) ----
__global__ __launch_bounds__(1024) void k_label_init() {
    __shared__ int sc[1024];
    int t = threadIdx.x, base = t * 16, cnt = 0;
#pragma unroll
    for (int e = 0; e < 16; e++) cnt += g_root[base + e];
    sc[t] = cnt;
    __syncthreads();
    for (int off = 1; off < 1024; off <<= 1) {
        int v = (t >= off) ? sc[t - off] : 0;
        __syncthreads();
        sc[t] += v;
        __syncthreads();
    }
    int run = sc[t] - cnt;
#pragma unroll
    for (int e = 0; e < 16; e++) {
        int x = base + e;
        if (g_root[x]) { g_labval[x] = 1 + run; run++; g_ptrA[x] = x; }
        else { g_labval[x] = 0; g_ptrA[x] = (x & ~(NPT - 1)) + g_p[x]; }
    }
    if (t == 1023) g_Rtot = sc[1023];
}

// ---- 4b: one pointer-jumping step, grid-wide (launch boundary = grid sync) ----
__global__ void k_jump(int phase) {
    int x = blockIdx.x * blockDim.x + threadIdx.x;
    if (phase == 0) g_ptrB[x] = g_ptrA[g_ptrA[x]];
    else            g_ptrA[x] = g_ptrB[g_ptrB[x]];
}

// ---- 4c/4d: finalize v then labels ----
__global__ void k_vfin() {
    int x = blockIdx.x * blockDim.x + threadIdx.x;
    g_v[x] = g_labval[g_ptrA[x]];
}
__global__ void k_labfin() {
    int x = blockIdx.x * blockDim.x + threadIdx.x;
    g_labels[x] = g_v[(x & ~(NPT - 1)) + g_q[x]];
}

// ---- 5: histogram / unique / cooperative stable member compaction ----
__global__ __launch_bounds__(1024) void k_build() {
    __shared__ int wcnt[32], wpre[32], sTot, sWritten;
    int t = threadIdx.x, lane = t & 31, wid = t >> 5;
    for (int i = t; i < NB * (NTOT + 1); i += 1024) (&g_hist[0][0])[i] = 0;
    __syncthreads();
#pragma unroll
    for (int e = 0; e < 16; e++) {
        int x = t * 16 + e;
        atomicAdd(&g_hist[x >> 12][g_labels[x]], 1);
    }
    __syncthreads();
    int R = g_Rtot;
    if (t < NB) {
        int k = 0;
        for (int l = 1; l <= R; l++) if (g_hist[t][l] > 0) { g_map[t][l] = k; k++; }
        g_Kb[t] = k;
    }
    __syncthreads();
    if (t == 0) {
        int s = 0;
        for (int b = 0; b < NB; b++) { g_KbBase[b] = s; s += g_Kb[b]; }
        g_Ktot = s;
    }
    __syncthreads();
    if (t < NB) {
        int b = t, off = 0, k = 0;
        for (int l = 1; l <= R; l++) {
            int c = g_hist[b][l];
            if (c > 0) {
                int slot = g_KbBase[b] + k;
                g_clusM[slot] = c; g_clusB[slot] = b;
                g_clusBase[slot] = b * NPT + off; g_clusL[slot] = l;
                off += c; k++;
            }
        }
    }
    __syncthreads();
    // cooperative stable compaction: members in ascending-j order per cluster
    int K = g_Ktot;
    for (int slot = 0; slot < K; slot++) {
        int b = g_clusB[slot], l = g_clusL[slot], base = g_clusBase[slot];
        if (t == 0) sWritten = 0;
        __syncthreads();
        for (int chunk = 0; chunk < NPT; chunk += 1024) {
            int j = chunk + t;
            bool m = (g_labels[b * NPT + j] == l);
            unsigned int bal = __ballot_sync(0xffffffffu, m);
            int lp = __popc(bal & ((1u << lane) - 1));
            if (lane == 0) wcnt[wid] = __popc(bal);
            __syncthreads();
            if (t == 0) {
                int s = 0;
                for (int w = 0; w < 32; w++) { wpre[w] = s; s += wcnt[w]; }
                sTot = s;
            }
            __syncthreads();
            if (m) g_members[base + sWritten + wpre[wid] + lp] = j;
            __syncthreads();
            if (t == 0) sWritten += sTot;
            __syncthreads();
        }
    }
}

// ---- 6: numpy RandomState(0).choice replay (MT19937, legacy masked rejection) ----
__global__ void k_rng() {
    unsigned int key[624];
    unsigned int s = 0u;
    for (int i = 0; i < 624; i++) { key[i] = s; s = 1812433253u * (s ^ (s >> 30)) + (unsigned)i + 1u; }
    int pos = 624;
    int K = g_Ktot;
    for (int slot = 0; slot < K; slot++) {
        int M = g_clusM[slot], b = g_clusB[slot], base = g_clusBase[slot];
        if (M <= 1) {
            int gj = b * NPT + g_members[base];
            for (int tt = 0; tt < DS; tt++) g_gidx[slot * DS + tt] = gj;
        } else {
            unsigned int rng = (unsigned int)(M - 1), mask = rng;
            mask |= mask >> 1; mask |= mask >> 2; mask |= mask >> 4; mask |= mask >> 8; mask |= mask >> 16;
            for (int tt = 0; tt < DS; tt++) {
                unsigned int r;
                do {
                    if (pos == 624) {
                        for (int i = 0; i < 624; i++) {
                            unsigned int y = (key[i] & 0x80000000u) | (key[(i + 1) % 624] & 0x7fffffffu);
                            unsigned int v = key[(i + 397) % 624] ^ (y >> 1);
                            key[i] = (y & 1u) ? (v ^ 0x9908b0dfu) : v;
                        }
                        pos = 0;
                    }
                    unsigned int y = key[pos++];
                    y ^= y >> 11; y ^= (y << 7) & 0x9d2c5680u; y ^= (y << 15) & 0xefc60000u; y ^= y >> 18;
                    r = y & mask;
                } while (r > rng);
                g_gidx[slot * DS + tt] = b * NPT + g_members[base + (int)r];
            }
        }
    }
}

// ---- 7: PointNet-lite classifier + BCE ----
__global__ __launch_bounds__(128) void k_classify(const float* __restrict__ pts,
        const float* __restrict__ W1, const float* __restrict__ b1,
        const float* __restrict__ W2, const float* __restrict__ b2,
        const float* __restrict__ W3, const float* __restrict__ b3,
        float* __restrict__ out) {
    __shared__ float sW1[192], sb1[64], sW3[256], sb3[2];
    __shared__ float sp[240];
    __shared__ float sh1[80 * 64];
    __shared__ float sred[128];
    int t = threadIdx.x;
    for (int i = t; i < 192; i += 128) sW1[i] = W1[i];
    if (t < 64) sb1[t] = b1[t];
    for (int i = t; i < 256; i += 128) sW3[i] = W3[i];
    if (t < 2) sb3[t] = b3[t];
    float rW2[64];
#pragma unroll
    for (int k = 0; k < 64; k++) rW2[k] = W2[k * 128 + t];
    float rb2 = b2[t];
    __syncthreads();
    int K = g_Ktot;
    for (int slot = blockIdx.x; slot < K; slot += gridDim.x) {
        for (int i = t; i < 240; i += 128) {
            int pt = i / 3, f = i - pt * 3;
            sp[i] = pts[(size_t)g_gidx[slot * DS + pt] * 3 + f];
        }
        __syncthreads();
        for (int o = t; o < 80 * 64; o += 128) {
            int pt = o >> 6, c = o & 63;
            float a = sb1[c] + sp[pt * 3] * sW1[c] + sp[pt * 3 + 1] * sW1[64 + c] + sp[pt * 3 + 2] * sW1[128 + c];
            sh1[o] = fmaxf(a, 0.f);
        }
        __syncthreads();
        float m = -3.402823466e38f;
        for (int pt = 0; pt < 80; pt++) {
            const float* h = &sh1[pt * 64];
            float a = rb2;
#pragma unroll
            for (int k = 0; k < 64; k++) a = fmaf(h[k], rW2[k], a);
            m = fmaxf(m, a);
        }
        float gt = fmaxf(m, 0.f);
        sred[t] = gt * sW3[2 * t];
        __syncthreads();
        for (int off = 64; off; off >>= 1) { if (t < off) sred[t] += sred[t + off]; __syncthreads(); }
        float l0 = sred[0] + sb3[0];
        __syncthreads();
        sred[t] = gt * sW3[2 * t + 1];
        __syncthreads();
        for (int off = 64; off; off >>= 1) { if (t < off) sred[t] += sred[t + off]; __syncthreads(); }
        if (t == 0) {
            float l1 = sred[0] + sb3[1];
            float loss = fminf(log1pf(expf(l0 - l1)), 100.f);
            atomicAdd(out, loss / (float)g_Kb[g_clusB[slot]]);
        }
        __syncthreads();
    }
}

extern "C" void kernel_launch(void* const* d_in, const int* in_sizes, int n_in,
                              void* d_out, int out_size) {
    const float* feat = (const float*)d_in[0];
    const float* pts  = (const float*)d_in[1];
    const float* W1 = (const float*)d_in[2];
    const float* b1 = (const float*)d_in[3];
    const float* W2 = (const float*)d_in[4];
    const float* b2 = (const float*)d_in[5];
    const float* W3 = (const float*)d_in[6];
    const float* b3 = (const float*)d_in[7];
    float* out = (float*)d_out;
    k_sq<<<NTOT * 32 / 256, 256>>>(feat, out);
    k_gemm<<<dim3(NPT / 128, NPT / 128, NB), 256>>>(feat);
    k_rowpq<<<NTOT * 32 / 256, 256>>>();
    k_label_init<<<1, 1024>>>();
    for (int it = 0; it < 12; it++) k_jump<<<NTOT / 256, 256>>>(it & 1);
    k_vfin<<<NTOT / 256, 256>>>();
    k_labfin<<<NTOT / 256, 256>>>();
    k_build<<<1, 1024>>>();
    k_rng<<<1, 1>>>();
    k_classify<<<32, 128>>>(pts, W1, b1, W2, b2, W3, b3, out);
}

// round 5
// speedup vs baseline: 2.1229x; 1.3068x over previous
#include <cuda_runtime.h>
#include <cuda_bf16.h>
#include <cstdint>
#include <math.h>

#define NB 4
#define NPT 4096
#define NF 256
#define NTOT (NB*NPT)
#define DS 80
#define NTILE 32
#define NTRI (NTILE*(NTILE+1)/2)

__device__ unsigned char g_adj[(size_t)NTOT * NPT];
__device__ __nv_bfloat16 g_hi[(size_t)NTOT * NF];
__device__ __nv_bfloat16 g_lo[(size_t)NTOT * NF];
__device__ float g_sq[NTOT];
__device__ int g_p[NTOT], g_q[NTOT], g_root[NTOT], g_labval[NTOT];
__device__ int g_ptrA[NTOT], g_ptrB[NTOT], g_v[NTOT], g_labels[NTOT];
__device__ int g_ccnt[64], g_coff[64];
__device__ int g_hist[NB][NTOT + 1];
__device__ int g_map[NB][NTOT + 1];
__device__ int g_members[NTOT];
__device__ int g_clusM[NTOT], g_clusB[NTOT], g_clusBase[NTOT], g_clusL[NTOT];
__device__ int g_Kb[NB], g_KbBase[NB], g_Ktot, g_Rtot;
__device__ int g_gidx[(size_t)NTOT * DS];

__device__ __forceinline__ uint32_t smem_u32(const void* p) {
    uint32_t a;
    asm("{ .reg .u64 t; cvta.to.shared.u64 t, %1; cvt.u32.u64 %0, t; }" : "=r"(a) : "l"(p));
    return a;
}
__device__ __forceinline__ void ldsm4(uint32_t* r, uint32_t a) {
    asm volatile("ldmatrix.sync.aligned.m8n8.x4.shared.b16 {%0,%1,%2,%3}, [%4];"
        : "=r"(r[0]), "=r"(r[1]), "=r"(r[2]), "=r"(r[3]) : "r"(a));
}
__device__ __forceinline__ void ldsm2(uint32_t* r, uint32_t a) {
    asm volatile("ldmatrix.sync.aligned.m8n8.x2.shared.b16 {%0,%1}, [%2];"
        : "=r"(r[0]), "=r"(r[1]) : "r"(a));
}
__device__ __forceinline__ void mma16816(float* c, const uint32_t* a, const uint32_t* b) {
    asm volatile("mma.sync.aligned.m16n8k16.row.col.f32.bf16.bf16.f32 "
        "{%0,%1,%2,%3},{%4,%5,%6,%7},{%8,%9},{%0,%1,%2,%3};"
        : "+f"(c[0]), "+f"(c[1]), "+f"(c[2]), "+f"(c[3])
        : "r"(a[0]), "r"(a[1]), "r"(a[2]), "r"(a[3]), "r"(b[0]), "r"(b[1]));
}

#define STR 80              /* smem row stride bytes (40 bf16) */
#define OP_A 0
#define OP_B 10240
#define ST_N 0
#define ST_T 16896
#define OFF_SQJ 33792
#define SMEM_DYN 34304

// ---- 0: fp32 -> bf16 hi/lo split ----
__global__ void k_cvt(const float* __restrict__ feat) {
    size_t i = ((size_t)blockIdx.x * blockDim.x + threadIdx.x) * 2;
    float x0 = feat[i], x1 = feat[i + 1];
    __nv_bfloat16 h0 = __float2bfloat16_rn(x0), h1 = __float2bfloat16_rn(x1);
    __nv_bfloat16 l0 = __float2bfloat16_rn(x0 - __bfloat162float(h0));
    __nv_bfloat16 l1 = __float2bfloat16_rn(x1 - __bfloat162float(h1));
    __nv_bfloat162 hp; hp.x = h0; hp.y = h1;
    __nv_bfloat162 lp; lp.x = l0; lp.y = l1;
    *(__nv_bfloat162*)(&g_hi[i]) = hp;
    *(__nv_bfloat162*)(&g_lo[i]) = lp;
}

// ---- 1: row sums of squares (+ zero output) ----
__global__ void k_sq(const float* __restrict__ feat, float* __restrict__ out) {
    int gt = blockIdx.x * blockDim.x + threadIdx.x;
    if (gt == 0) out[0] = 0.f;
    int w = gt >> 5, lane = gt & 31;
    const float* r = feat + (size_t)w * NF;
    float s = 0.f;
#pragma unroll
    for (int t = 0; t < NF / 32; t++) { float x = r[t * 32 + lane]; s = fmaf(x, x, s); }
#pragma unroll
    for (int o = 16; o; o >>= 1) s += __shfl_xor_sync(0xffffffffu, s, o);
    if (lane == 0) g_sq[w] = s;
}

// ---- 2: bf16-split HMMA GEMM -> adjacency tile ----
__global__ __launch_bounds__(256, 1) void k_mma() {
    extern __shared__ char sb[];
    uint32_t s0 = smem_u32(sb);
    int t = threadIdx.x, wid = t >> 5, l = t & 31;
    int wm = wid >> 2, wn = wid & 3;
    int ti = blockIdx.x, bi = 0;
    while (ti >= NTILE - bi) { ti -= NTILE - bi; bi++; }
    int bj = bi + ti;
    int b = blockIdx.y;
    int iBase = bi * 128, jBase = bj * 128;
    bool diag = (bi == bj);

    if (t < 128) ((float*)(sb + OFF_SQJ))[t] = g_sq[b * NPT + jBase + t];

    const __nv_bfloat16* Ahi = g_hi + (size_t)(b * NPT + iBase) * NF;
    const __nv_bfloat16* Alo = g_lo + (size_t)(b * NPT + iBase) * NF;
    const __nv_bfloat16* Bhi = g_hi + (size_t)(b * NPT + jBase) * NF;
    const __nv_bfloat16* Blo = g_lo + (size_t)(b * NPT + jBase) * NF;

    float acc[4][4][4];
#pragma unroll
    for (int mt = 0; mt < 4; mt++)
#pragma unroll
        for (int nt = 0; nt < 4; nt++)
#pragma unroll
            for (int r = 0; r < 4; r++) acc[mt][nt][r] = 0.f;

    int lrow = t >> 1, lh = t & 1;
#pragma unroll 1
    for (int sp = 0; sp < 3; sp++) {
        const __nv_bfloat16* SA = (sp == 2) ? Alo : Ahi;
        const __nv_bfloat16* SB = (sp == 1) ? Blo : Bhi;
#pragma unroll 1
        for (int c = 0; c < 8; c++) {
            __syncthreads();
            *(uint4*)(sb + OP_A + lrow * STR + lh * 16) = *(const uint4*)(SA + (size_t)lrow * NF + c * 32 + lh * 8);
            *(uint4*)(sb + OP_B + lrow * STR + lh * 16) = *(const uint4*)(SB + (size_t)lrow * NF + c * 32 + lh * 8);
            __syncthreads();
#pragma unroll
            for (int kk = 0; kk < 2; kk++) {
                uint32_t af[4][4], bfr[4][2];
#pragma unroll
                for (int mt = 0; mt < 4; mt++)
                    ldsm4(af[mt], s0 + OP_A + (wm * 64 + mt * 16 + (l & 15)) * STR + kk * 32 + (l >> 4) * 16);
#pragma unroll
                for (int nt = 0; nt < 4; nt++)
                    ldsm2(bfr[nt], s0 + OP_B + (wn * 32 + nt * 8 + (l & 7)) * STR + kk * 32 + ((l >> 3) & 1) * 16);
#pragma unroll
                for (int mt = 0; mt < 4; mt++)
#pragma unroll
                    for (int nt = 0; nt < 4; nt++)
                        mma16816(acc[mt][nt], af[mt], bfr[nt]);
            }
        }
    }
    __syncthreads();

    // epilogue: threshold -> bytes (normal + transposed staging)
    int g = l >> 2, tg = l & 3;
    float sqia[8];
#pragma unroll
    for (int mt = 0; mt < 4; mt++)
#pragma unroll
        for (int h = 0; h < 2; h++)
            sqia[mt * 2 + h] = g_sq[b * NPT + iBase + wm * 64 + mt * 16 + g + h * 8];
    const float* sqj = (const float*)(sb + OFF_SQJ);
#pragma unroll
    for (int mt = 0; mt < 4; mt++)
#pragma unroll
        for (int nt = 0; nt < 4; nt++)
#pragma unroll
            for (int r = 0; r < 4; r++) {
                int row = wm * 64 + mt * 16 + g + (r >> 1) * 8;
                int col = wn * 32 + nt * 8 + tg * 2 + (r & 1);
                float d2 = sqia[mt * 2 + (r >> 1)] + sqj[col] - 2.f * acc[mt][nt][r];
                unsigned char bit = (sqrtf(fmaxf(d2, 0.f)) < 22.63f) ? 1 : 0;
                ((unsigned char*)sb)[ST_N + row * 132 + col] = bit;
                if (!diag) ((unsigned char*)sb)[ST_T + col * 132 + row] = bit;
            }
    __syncthreads();
    {
        unsigned char* dst = g_adj + (size_t)(b * NPT + iBase) * NPT + jBase;
        for (int idx = t; idx < 4096; idx += 256) {
            int r = idx >> 5, w = idx & 31;
            *(uint32_t*)(dst + (size_t)r * NPT + w * 4) = *(uint32_t*)(sb + ST_N + r * 132 + w * 4);
        }
        if (!diag) {
            unsigned char* dstT = g_adj + (size_t)(b * NPT + jBase) * NPT + iBase;
            for (int idx = t; idx < 4096; idx += 256) {
                int r = idx >> 5, w = idx & 31;
                *(uint32_t*)(dstT + (size_t)r * NPT + w * 4) = *(uint32_t*)(sb + ST_T + r * 132 + w * 4);
            }
        }
    }
}

// ---- 3: per-row p (last neighbor < j) and q (last neighbor) ----
__global__ void k_rowpq() {
    int gw = (blockIdx.x * blockDim.x + threadIdx.x) >> 5;
    int lane = threadIdx.x & 31;
    int j = gw & (NPT - 1);
    const uint4* row = (const uint4*)(g_adj + (size_t)gw * NPT);
    int pmax = -1, qmax = -1;
#pragma unroll
    for (int tI = 0; tI < 8; tI++) {
        uint4 v = row[tI * 32 + lane];
        int base = (tI * 32 + lane) * 16;
        unsigned int ws[4] = {v.x, v.y, v.z, v.w};
#pragma unroll
        for (int w = 0; w < 4; w++) {
            unsigned int word = ws[w];
            if (!word) continue;
#pragma unroll
            for (int bb = 0; bb < 4; bb++)
                if ((word >> (8 * bb)) & 0xFFu) {
                    int idx = base + w * 4 + bb;
                    qmax = max(qmax, idx);
                    if (idx < j) pmax = max(pmax, idx);
                }
        }
    }
#pragma unroll
    for (int o = 16; o; o >>= 1) {
        qmax = max(qmax, __shfl_xor_sync(0xffffffffu, qmax, o));
        pmax = max(pmax, __shfl_xor_sync(0xffffffffu, pmax, o));
    }
    if (lane == 0) { g_p[gw] = pmax; g_q[gw] = qmax; g_root[gw] = (pmax < 0); }
}

// ---- 4: root counting / scan / assignment / pointer jumping ----
__global__ void k_rcnt() {
    __shared__ int wsum[8];
    int t = threadIdx.x;
    int x = blockIdx.x * 256 + t;
    int r = g_root[x];
#pragma unroll
    for (int o = 16; o; o >>= 1) r += __shfl_xor_sync(0xffffffffu, r, o);
    if ((t & 31) == 0) wsum[t >> 5] = r;
    __syncthreads();
    if (t == 0) {
        int s = 0;
        for (int w = 0; w < 8; w++) s += wsum[w];
        g_ccnt[blockIdx.x] = s;
    }
}
__global__ void k_rscan() {
    if (threadIdx.x == 0) {
        int s = 0;
        for (int i = 0; i < 64; i++) { g_coff[i] = s; s += g_ccnt[i]; }
        g_Rtot = s;
    }
}
__global__ void k_assign() {
    __shared__ int woff[8];
    int t = threadIdx.x, lane = t & 31, wid = t >> 5;
    int x = blockIdx.x * 256 + t;
    int isr = g_root[x];
    unsigned int bal = __ballot_sync(0xffffffffu, isr);
    int lp = __popc(bal & ((1u << lane) - 1));
    if (lane == 0) woff[wid] = __popc(bal);
    __syncthreads();
    if (t == 0) {
        int s = 0;
        for (int w = 0; w < 8; w++) { int c = woff[w]; woff[w] = s; s += c; }
    }
    __syncthreads();
    if (isr) { g_labval[x] = 1 + g_coff[blockIdx.x] + woff[wid] + lp; g_ptrA[x] = x; }
    else { g_labval[x] = 0; g_ptrA[x] = (x & ~(NPT - 1)) + g_p[x]; }
}
__global__ void k_jump(int phase) {
    int x = blockIdx.x * blockDim.x + threadIdx.x;
    if (phase == 0) g_ptrB[x] = g_ptrA[g_ptrA[x]];
    else            g_ptrA[x] = g_ptrB[g_ptrB[x]];
}
__global__ void k_vfin() {
    int x = blockIdx.x * blockDim.x + threadIdx.x;
    g_v[x] = g_labval[g_ptrA[x]];
}
__global__ void k_labfin() {
    int x = blockIdx.x * blockDim.x + threadIdx.x;
    g_labels[x] = g_v[(x & ~(NPT - 1)) + g_q[x]];
}

// ---- 5: histogram / unique / stable member compaction ----
__global__ __launch_bounds__(1024) void k_build() {
    __shared__ int wcnt[32], wpre[32], sTot, sWritten;
    int t = threadIdx.x, lane = t & 31, wid = t >> 5;
    for (int i = t; i < NB * (NTOT + 1); i += 1024) (&g_hist[0][0])[i] = 0;
    __syncthreads();
#pragma unroll
    for (int e = 0; e < 16; e++) {
        int x = t * 16 + e;
        atomicAdd(&g_hist[x >> 12][g_labels[x]], 1);
    }
    __syncthreads();
    int R = g_Rtot;
    if (t < NB) {
        int k = 0;
        for (int l = 1; l <= R; l++) if (g_hist[t][l] > 0) { g_map[t][l] = k; k++; }
        g_Kb[t] = k;
    }
    __syncthreads();
    if (t == 0) {
        int s = 0;
        for (int b = 0; b < NB; b++) { g_KbBase[b] = s; s += g_Kb[b]; }
        g_Ktot = s;
    }
    __syncthreads();
    if (t < NB) {
        int b = t, off = 0, k = 0;
        for (int l = 1; l <= R; l++) {
            int c = g_hist[b][l];
            if (c > 0) {
                int slot = g_KbBase[b] + k;
                g_clusM[slot] = c; g_clusB[slot] = b;
                g_clusBase[slot] = b * NPT + off; g_clusL[slot] = l;
                off += c; k++;
            }
        }
    }
    __syncthreads();
    int K = g_Ktot;
    for (int slot = 0; slot < K; slot++) {
        int b = g_clusB[slot], l = g_clusL[slot], base = g_clusBase[slot];
        if (t == 0) sWritten = 0;
        __syncthreads();
        for (int chunk = 0; chunk < NPT; chunk += 1024) {
            int j = chunk + t;
            bool m = (g_labels[b * NPT + j] == l);
            unsigned int bal = __ballot_sync(0xffffffffu, m);
            int lp = __popc(bal & ((1u << lane) - 1));
            if (lane == 0) wcnt[wid] = __popc(bal);
            __syncthreads();
            if (t == 0) {
                int s = 0;
                for (int w = 0; w < 32; w++) { wpre[w] = s; s += wcnt[w]; }
                sTot = s;
            }
            __syncthreads();
            if (m) g_members[base + sWritten + wpre[wid] + lp] = j;
            __syncthreads();
            if (t == 0) sWritten += sTot;
            __syncthreads();
        }
    }
}

// ---- 6: numpy RandomState(0).choice replay ----
__global__ void k_rng() {
    unsigned int key[624];
    unsigned int s = 0u;
    for (int i = 0; i < 624; i++) { key[i] = s; s = 1812433253u * (s ^ (s >> 30)) + (unsigned)i + 1u; }
    int pos = 624;
    int K = g_Ktot;
    for (int slot = 0; slot < K; slot++) {
        int M = g_clusM[slot], b = g_clusB[slot], base = g_clusBase[slot];
        if (M <= 1) {
            int gj = b * NPT + g_members[base];
            for (int tt = 0; tt < DS; tt++) g_gidx[slot * DS + tt] = gj;
        } else {
            unsigned int rng = (unsigned int)(M - 1), mask = rng;
            mask |= mask >> 1; mask |= mask >> 2; mask |= mask >> 4; mask |= mask >> 8; mask |= mask >> 16;
            for (int tt = 0; tt < DS; tt++) {
                unsigned int r;
                do {
                    if (pos == 624) {
                        for (int i = 0; i < 624; i++) {
                            unsigned int y = (key[i] & 0x80000000u) | (key[(i + 1) % 624] & 0x7fffffffu);
                            unsigned int v = key[(i + 397) % 624] ^ (y >> 1);
                            key[i] = (y & 1u) ? (v ^ 0x9908b0dfu) : v;
                        }
                        pos = 0;
                    }
                    unsigned int y = key[pos++];
                    y ^= y >> 11; y ^= (y << 7) & 0x9d2c5680u; y ^= (y << 15) & 0xefc60000u; y ^= y >> 18;
                    r = y & mask;
                } while (r > rng);
                g_gidx[slot * DS + tt] = b * NPT + g_members[base + (int)r];
            }
        }
    }
}

// ---- 7: PointNet-lite classifier + BCE ----
__global__ __launch_bounds__(128) void k_classify(const float* __restrict__ pts,
        const float* __restrict__ W1, const float* __restrict__ b1,
        const float* __restrict__ W2, const float* __restrict__ b2,
        const float* __restrict__ W3, const float* __restrict__ b3,
        float* __restrict__ out) {
    __shared__ float sW1[192], sb1[64], sW3[256], sb3[2];
    __shared__ float sp[240];
    __shared__ float sh1[80 * 64];
    __shared__ float sred[128];
    int t = threadIdx.x;
    for (int i = t; i < 192; i += 128) sW1[i] = W1[i];
    if (t < 64) sb1[t] = b1[t];
    for (int i = t; i < 256; i += 128) sW3[i] = W3[i];
    if (t < 2) sb3[t] = b3[t];
    float rW2[64];
#pragma unroll
    for (int k = 0; k < 64; k++) rW2[k] = W2[k * 128 + t];
    float rb2 = b2[t];
    __syncthreads();
    int K = g_Ktot;
    for (int slot = blockIdx.x; slot < K; slot += gridDim.x) {
        for (int i = t; i < 240; i += 128) {
            int pt = i / 3, f = i - pt * 3;
            sp[i] = pts[(size_t)g_gidx[slot * DS + pt] * 3 + f];
        }
        __syncthreads();
        for (int o = t; o < 80 * 64; o += 128) {
            int pt = o >> 6, c = o & 63;
            float a = sb1[c] + sp[pt * 3] * sW1[c] + sp[pt * 3 + 1] * sW1[64 + c] + sp[pt * 3 + 2] * sW1[128 + c];
            sh1[o] = fmaxf(a, 0.f);
        }
        __syncthreads();
        float m = -3.402823466e38f;
        for (int pt = 0; pt < 80; pt++) {
            const float* h = &sh1[pt * 64];
            float a = rb2;
#pragma unroll
            for (int k = 0; k < 64; k++) a = fmaf(h[k], rW2[k], a);
            m = fmaxf(m, a);
        }
        float gt = fmaxf(m, 0.f);
        sred[t] = gt * sW3[2 * t];
        __syncthreads();
        for (int off = 64; off; off >>= 1) { if (t < off) sred[t] += sred[t + off]; __syncthreads(); }
        float l0 = sred[0] + sb3[0];
        __syncthreads();
        sred[t] = gt * sW3[2 * t + 1];
        __syncthreads();
        for (int off = 64; off; off >>= 1) { if (t < off) sred[t] += sred[t + off]; __syncthreads(); }
        if (t == 0) {
            float l1 = sred[0] + sb3[1];
            float loss = fminf(log1pf(expf(l0 - l1)), 100.f);
            atomicAdd(out, loss / (float)g_Kb[g_clusB[slot]]);
        }
        __syncthreads();
    }
}

extern "C" void kernel_launch(void* const* d_in, const int* in_sizes, int n_in,
                              void* d_out, int out_size) {
    const float* feat = (const float*)d_in[0];
    const float* pts  = (const float*)d_in[1];
    const float* W1 = (const float*)d_in[2];
    const float* b1 = (const float*)d_in[3];
    const float* W2 = (const float*)d_in[4];
    const float* b2 = (const float*)d_in[5];
    const float* W3 = (const float*)d_in[6];
    const float* b3 = (const float*)d_in[7];
    float* out = (float*)d_out;
    k_cvt<<<(NTOT * NF / 2) / 256, 256>>>(feat);
    k_sq<<<NTOT * 32 / 256, 256>>>(feat, out);
    k_mma<<<dim3(NTRI, NB), 256, SMEM_DYN>>>();
    k_rowpq<<<NTOT * 32 / 256, 256>>>();
    k_rcnt<<<64, 256>>>();
    k_rscan<<<1, 32>>>();
    k_assign<<<64, 256>>>();
    for (int it = 0; it < 12; it++) k_jump<<<NTOT / 256, 256>>>(it & 1);
    k_vfin<<<NTOT / 256, 256>>>();
    k_labfin<<<NTOT / 256, 256>>>();
    k_build<<<1, 1024>>>();
    k_rng<<<1, 1>>>();
    k_classify<<<32, 128>>>(pts, W1, b1, W2, b2, W3, b3, out);
}

// round 7
// speedup vs baseline: 2.7942x; 1.3162x over previous
#include <cuda_runtime.h>
#include <cuda_bf16.h>
#include <cstdint>
#include <math.h>

#define NB 4
#define NPT 4096
#define NF 256
#define NTOT (NB*NPT)
#define DS 80
#define NTILE 32
#define NTRI (NTILE*(NTILE+1)/2)

__device__ uint32_t g_adj32[(size_t)NTOT * 128];
__device__ __nv_bfloat16 g_hi[(size_t)NTOT * NF];
__device__ __nv_bfloat16 g_lo[(size_t)NTOT * NF];
__device__ float g_sq[NTOT];
__device__ int g_p[NTOT], g_q[NTOT], g_root[NTOT], g_labval[NTOT];
__device__ int g_ptrA[NTOT], g_ptrB[NTOT], g_v[NTOT], g_labels[NTOT];
__device__ int g_ccnt[64], g_coff[64];
__device__ int g_hist[NB][NTOT + 1];
__device__ int g_map[NB][NTOT + 1];
__device__ int g_members[NTOT];
__device__ int g_clusM[NTOT], g_clusB[NTOT], g_clusBase[NTOT], g_clusL[NTOT];
__device__ int g_Kb[NB], g_KbBase[NB], g_Ktot, g_Rtot;
__device__ int g_gidx[(size_t)NTOT * DS];

__device__ __forceinline__ uint32_t smem_u32(const void* p) {
    uint32_t a;
    asm("{ .reg .u64 t; cvta.to.shared.u64 t, %1; cvt.u32.u64 %0, t; }" : "=r"(a) : "l"(p));
    return a;
}
__device__ __forceinline__ void cp16(uint32_t dst, const void* src) {
    asm volatile("cp.async.ca.shared.global [%0], [%1], 16;" :: "r"(dst), "l"(src));
}
__device__ __forceinline__ void cp_commit() { asm volatile("cp.async.commit_group;"); }
__device__ __forceinline__ void cp_wait1() { asm volatile("cp.async.wait_group 1;"); }
__device__ __forceinline__ void cp_wait0() { asm volatile("cp.async.wait_group 0;"); }
__device__ __forceinline__ void ldsm4(uint32_t* r, uint32_t a) {
    asm volatile("ldmatrix.sync.aligned.m8n8.x4.shared.b16 {%0,%1,%2,%3}, [%4];"
        : "=r"(r[0]), "=r"(r[1]), "=r"(r[2]), "=r"(r[3]) : "r"(a));
}
__device__ __forceinline__ void ldsm2(uint32_t* r, uint32_t a) {
    asm volatile("ldmatrix.sync.aligned.m8n8.x2.shared.b16 {%0,%1}, [%2];"
        : "=r"(r[0]), "=r"(r[1]) : "r"(a));
}
__device__ __forceinline__ void mma16816(float* c, const uint32_t* a, const uint32_t* b) {
    asm volatile("mma.sync.aligned.m16n8k16.row.col.f32.bf16.bf16.f32 "
        "{%0,%1,%2,%3},{%4,%5,%6,%7},{%8,%9},{%0,%1,%2,%3};"
        : "+f"(c[0]), "+f"(c[1]), "+f"(c[2]), "+f"(c[3])
        : "r"(a[0]), "r"(a[1]), "r"(a[2]), "r"(a[3]), "r"(b[0]), "r"(b[1]));
}

#define STR 80        /* smem row stride bytes */
#define STG 40960     /* bytes per pipeline stage (4 tensors x 128 x 80) */
#define T_AHI 0
#define T_ALO 10240
#define T_BHI 20480
#define T_BLO 30720
#define OFF_SQJ 81920
#define SMEM_DYN 82432
#define ST_N 0
#define ST_T 16896

// ---- 0: fp32 -> bf16 hi/lo split ----
__global__ void k_cvt(const float* __restrict__ feat) {
    size_t i = ((size_t)blockIdx.x * blockDim.x + threadIdx.x) * 2;
    float x0 = feat[i], x1 = feat[i + 1];
    __nv_bfloat16 h0 = __float2bfloat16_rn(x0), h1 = __float2bfloat16_rn(x1);
    __nv_bfloat16 l0 = __float2bfloat16_rn(x0 - __bfloat162float(h0));
    __nv_bfloat16 l1 = __float2bfloat16_rn(x1 - __bfloat162float(h1));
    __nv_bfloat162 hp; hp.x = h0; hp.y = h1;
    __nv_bfloat162 lp; lp.x = l0; lp.y = l1;
    *(__nv_bfloat162*)(&g_hi[i]) = hp;
    *(__nv_bfloat162*)(&g_lo[i]) = lp;
}

// ---- 1: row sums of squares (+ zero output) ----
__global__ void k_sq(const float* __restrict__ feat, float* __restrict__ out) {
    int gt = blockIdx.x * blockDim.x + threadIdx.x;
    if (gt == 0) out[0] = 0.f;
    int w = gt >> 5, lane = gt & 31;
    const float* r = feat + (size_t)w * NF;
    float s = 0.f;
#pragma unroll
    for (int t = 0; t < NF / 32; t++) { float x = r[t * 32 + lane]; s = fmaf(x, x, s); }
#pragma unroll
    for (int o = 16; o; o >>= 1) s += __shfl_xor_sync(0xffffffffu, s, o);
    if (lane == 0) g_sq[w] = s;
}

// ---- 2: bf16-split HMMA GEMM, cp.async double-buffered -> packed adjacency ----
__global__ __launch_bounds__(256, 1) void k_mma() {
    extern __shared__ char sb[];
    uint32_t s0 = smem_u32(sb);
    int t = threadIdx.x, wid = t >> 5, l = t & 31;
    int wm = wid >> 2, wn = wid & 3;
    int ti = blockIdx.x, bi = 0;
    while (ti >= NTILE - bi) { ti -= NTILE - bi; bi++; }
    int bj = bi + ti;
    int b = blockIdx.y;
    int iBase = bi * 128, jBase = bj * 128;
    bool diag = (bi == bj);

    if (t < 128) ((float*)(sb + OFF_SQJ))[t] = g_sq[b * NPT + jBase + t];

    const __nv_bfloat16* Ahi = g_hi + (size_t)(b * NPT + iBase) * NF;
    const __nv_bfloat16* Alo = g_lo + (size_t)(b * NPT + iBase) * NF;
    const __nv_bfloat16* Bhi = g_hi + (size_t)(b * NPT + jBase) * NF;
    const __nv_bfloat16* Blo = g_lo + (size_t)(b * NPT + jBase) * NF;

    float acc[4][4][4];
#pragma unroll
    for (int mt = 0; mt < 4; mt++)
#pragma unroll
        for (int nt = 0; nt < 4; nt++)
#pragma unroll
            for (int r = 0; r < 4; r++) acc[mt][nt][r] = 0.f;

    int row = t >> 1, half = t & 1;
    uint32_t dce = s0 + row * STR + half * 32;
    size_t gce = (size_t)row * NF + half * 16;

    // prologue: chunk 0 into stage 0
    {
        cp16(dce + T_AHI, Ahi + gce); cp16(dce + T_AHI + 16, Ahi + gce + 8);
        cp16(dce + T_ALO, Alo + gce); cp16(dce + T_ALO + 16, Alo + gce + 8);
        cp16(dce + T_BHI, Bhi + gce); cp16(dce + T_BHI + 16, Bhi + gce + 8);
        cp16(dce + T_BLO, Blo + gce); cp16(dce + T_BLO + 16, Blo + gce + 8);
        cp_commit();
    }
#pragma unroll 1
    for (int c = 0; c < 8; c++) {
        __syncthreads();   // prior mma done before overwriting other stage
        if (c < 7) {
            uint32_t d = dce + ((c + 1) & 1) * STG;
            size_t g2 = gce + (size_t)(c + 1) * 32;
            cp16(d + T_AHI, Ahi + g2); cp16(d + T_AHI + 16, Ahi + g2 + 8);
            cp16(d + T_ALO, Alo + g2); cp16(d + T_ALO + 16, Alo + g2 + 8);
            cp16(d + T_BHI, Bhi + g2); cp16(d + T_BHI + 16, Bhi + g2 + 8);
            cp16(d + T_BLO, Blo + g2); cp16(d + T_BLO + 16, Blo + g2 + 8);
            cp_commit();
            cp_wait1();
        } else {
            cp_wait0();
        }
        __syncthreads();
        uint32_t stg = s0 + (c & 1) * STG;
#pragma unroll
        for (int sp = 0; sp < 3; sp++) {
            uint32_t ab = stg + ((sp == 2) ? T_ALO : T_AHI);
            uint32_t bb = stg + ((sp == 1) ? T_BLO : T_BHI);
#pragma unroll
            for (int kk = 0; kk < 2; kk++) {
                uint32_t af[4][4], bfr[4][2];
#pragma unroll
                for (int mt = 0; mt < 4; mt++)
                    ldsm4(af[mt], ab + (wm * 64 + mt * 16 + (l & 15)) * STR + kk * 32 + (l >> 4) * 16);
#pragma unroll
                for (int nt = 0; nt < 4; nt++)
                    ldsm2(bfr[nt], bb + (wn * 32 + nt * 8 + (l & 7)) * STR + kk * 32 + ((l >> 3) & 1) * 16);
#pragma unroll
                for (int mt = 0; mt < 4; mt++)
#pragma unroll
                    for (int nt = 0; nt < 4; nt++)
                        mma16816(acc[mt][nt], af[mt], bfr[nt]);
            }
        }
    }
    __syncthreads();

    // epilogue: threshold -> byte staging (normal + transposed)
    int g = l >> 2, tg = l & 3;
    float sqia[8];
#pragma unroll
    for (int mt = 0; mt < 4; mt++)
#pragma unroll
        for (int h = 0; h < 2; h++)
            sqia[mt * 2 + h] = g_sq[b * NPT + iBase + wm * 64 + mt * 16 + g + h * 8];
    const float* sqj = (const float*)(sb + OFF_SQJ);
#pragma unroll
    for (int mt = 0; mt < 4; mt++)
#pragma unroll
        for (int nt = 0; nt < 4; nt++)
#pragma unroll
            for (int r = 0; r < 4; r++) {
                int ro = wm * 64 + mt * 16 + g + (r >> 1) * 8;
                int co = wn * 32 + nt * 8 + tg * 2 + (r & 1);
                float d2 = sqia[mt * 2 + (r >> 1)] + sqj[co] - 2.f * acc[mt][nt][r];
                unsigned char bit = (sqrtf(fmaxf(d2, 0.f)) < 22.63f) ? 1 : 0;
                ((unsigned char*)sb)[ST_N + ro * 132 + co] = bit;
                if (!diag) ((unsigned char*)sb)[ST_T + co * 132 + ro] = bit;
            }
    __syncthreads();
    // pack bytes -> bits, store words
    for (int idx = t; idx < 512; idx += 256) {
        int r = idx >> 2, wc = idx & 3;
        const uint32_t* src = (const uint32_t*)(sb + ST_N + r * 132 + wc * 32);
        uint32_t bits = 0;
#pragma unroll
        for (int i = 0; i < 8; i++) {
            uint32_t u = src[i];
            bits |= ((u & 1) | ((u >> 7) & 2) | ((u >> 14) & 4) | ((u >> 21) & 8)) << (4 * i);
        }
        g_adj32[(size_t)(b * NPT + iBase + r) * 128 + (jBase >> 5) + wc] = bits;
    }
    if (!diag) {
        for (int idx = t; idx < 512; idx += 256) {
            int r = idx >> 2, wc = idx & 3;
            const uint32_t* src = (const uint32_t*)(sb + ST_T + r * 132 + wc * 32);
            uint32_t bits = 0;
#pragma unroll
            for (int i = 0; i < 8; i++) {
                uint32_t u = src[i];
                bits |= ((u & 1) | ((u >> 7) & 2) | ((u >> 14) & 4) | ((u >> 21) & 8)) << (4 * i);
            }
            g_adj32[(size_t)(b * NPT + jBase + r) * 128 + (iBase >> 5) + wc] = bits;
        }
    }
}

// ---- 3: per-row p (last neighbor < j) and q (last neighbor) over bit rows ----
__global__ void k_rowpq() {
    int gw = (blockIdx.x * blockDim.x + threadIdx.x) >> 5;
    int lane = threadIdx.x & 31;
    int j = gw & (NPT - 1);
    const uint4* rp = (const uint4*)(g_adj32 + (size_t)gw * 128);
    uint4 v = rp[lane];
    uint32_t ws[4] = {v.x, v.y, v.z, v.w};
    int pmax = -1, qmax = -1;
    int jw = j >> 5, jb = j & 31;
#pragma unroll
    for (int k = 0; k < 4; k++) {
        int wi = lane * 4 + k;
        uint32_t w = ws[k];
        if (w) qmax = max(qmax, wi * 32 + 31 - __clz(w));
        uint32_t mp = (wi < jw) ? w : ((wi == jw && jb) ? (w & ((1u << jb) - 1)) : 0u);
        if (mp) pmax = max(pmax, wi * 32 + 31 - __clz(mp));
    }
#pragma unroll
    for (int o = 16; o; o >>= 1) {
        qmax = max(qmax, __shfl_xor_sync(0xffffffffu, qmax, o));
        pmax = max(pmax, __shfl_xor_sync(0xffffffffu, pmax, o));
    }
    if (lane == 0) { g_p[gw] = pmax; g_q[gw] = qmax; g_root[gw] = (pmax < 0); }
}

// ---- 4: root counting / scan / assignment / quad pointer jumping ----
__global__ void k_rcnt() {
    __shared__ int wsum[8];
    int t = threadIdx.x;
    int x = blockIdx.x * 256 + t;
    int r = g_root[x];
#pragma unroll
    for (int o = 16; o; o >>= 1) r += __shfl_xor_sync(0xffffffffu, r, o);
    if ((t & 31) == 0) wsum[t >> 5] = r;
    __syncthreads();
    if (t == 0) {
        int s = 0;
        for (int w = 0; w < 8; w++) s += wsum[w];
        g_ccnt[blockIdx.x] = s;
    }
}
__global__ void k_rscan() {
    if (threadIdx.x == 0) {
        int s = 0;
        for (int i = 0; i < 64; i++) { g_coff[i] = s; s += g_ccnt[i]; }
        g_Rtot = s;
    }
}
__global__ void k_assign() {
    __shared__ int woff[8];
    int t = threadIdx.x, lane = t & 31, wid = t >> 5;
    int x = blockIdx.x * 256 + t;
    int isr = g_root[x];
    unsigned int bal = __ballot_sync(0xffffffffu, isr);
    int lp = __popc(bal & ((1u << lane) - 1));
    if (lane == 0) woff[wid] = __popc(bal);
    __syncthreads();
    if (t == 0) {
        int s = 0;
        for (int w = 0; w < 8; w++) { int c = woff[w]; woff[w] = s; s += c; }
    }
    __syncthreads();
    if (isr) { g_labval[x] = 1 + g_coff[blockIdx.x] + woff[wid] + lp; g_ptrA[x] = x; }
    else { g_labval[x] = 0; g_ptrA[x] = (x & ~(NPT - 1)) + g_p[x]; }
}
__global__ void k_jump4(int phase) {
    int x = blockIdx.x * blockDim.x + threadIdx.x;
    if (phase == 0) {
        int a = g_ptrA[x]; a = g_ptrA[a]; a = g_ptrA[a]; a = g_ptrA[a];
        g_ptrB[x] = a;
    } else {
        int a = g_ptrB[x]; a = g_ptrB[a]; a = g_ptrB[a]; a = g_ptrB[a];
        g_ptrA[x] = a;
    }
}
__global__ void k_vfin() {
    int x = blockIdx.x * blockDim.x + threadIdx.x;
    g_v[x] = g_labval[g_ptrA[x]];
}
__global__ void k_labfin() {
    int x = blockIdx.x * blockDim.x + threadIdx.x;
    g_labels[x] = g_v[(x & ~(NPT - 1)) + g_q[x]];
}

// ---- 5: histogram / unique / stable member compaction ----
__global__ __launch_bounds__(1024) void k_build() {
    __shared__ int wcnt[32], wpre[32], sTot, sWritten;
    int t = threadIdx.x, lane = t & 31, wid = t >> 5;
    for (int i = t; i < NB * (NTOT + 1); i += 1024) (&g_hist[0][0])[i] = 0;
    __syncthreads();
#pragma unroll
    for (int e = 0; e < 16; e++) {
        int x = t * 16 + e;
        atomicAdd(&g_hist[x >> 12][g_labels[x]], 1);
    }
    __syncthreads();
    int R = g_Rtot;
    if (t < NB) {
        int k = 0;
        for (int l = 1; l <= R; l++) if (g_hist[t][l] > 0) { g_map[t][l] = k; k++; }
        g_Kb[t] = k;
    }
    __syncthreads();
    if (t == 0) {
        int s = 0;
        for (int b = 0; b < NB; b++) { g_KbBase[b] = s; s += g_Kb[b]; }
        g_Ktot = s;
    }
    __syncthreads();
    if (t < NB) {
        int b = t, off = 0, k = 0;
        for (int l = 1; l <= R; l++) {
            int c = g_hist[b][l];
            if (c > 0) {
                int slot = g_KbBase[b] + k;
                g_clusM[slot] = c; g_clusB[slot] = b;
                g_clusBase[slot] = b * NPT + off; g_clusL[slot] = l;
                off += c; k++;
            }
        }
    }
    __syncthreads();
    int K = g_Ktot;
    for (int slot = 0; slot < K; slot++) {
        int b = g_clusB[slot], l = g_clusL[slot], base = g_clusBase[slot];
        if (t == 0) sWritten = 0;
        __syncthreads();
        for (int chunk = 0; chunk < NPT; chunk += 1024) {
            int j = chunk + t;
            bool m = (g_labels[b * NPT + j] == l);
            unsigned int bal = __ballot_sync(0xffffffffu, m);
            int lp = __popc(bal & ((1u << lane) - 1));
            if (lane == 0) wcnt[wid] = __popc(bal);
            __syncthreads();
            if (t == 0) {
                int s = 0;
                for (int w = 0; w < 32; w++) { wpre[w] = s; s += wcnt[w]; }
                sTot = s;
            }
            __syncthreads();
            if (m) g_members[base + sWritten + wpre[wid] + lp] = j;
            __syncthreads();
            if (t == 0) sWritten += sTot;
            __syncthreads();
        }
    }
}

// ---- 6: numpy RandomState(0).choice replay ----
__global__ void k_rng() {
    unsigned int key[624];
    unsigned int s = 0u;
    for (int i = 0; i < 624; i++) { key[i] = s; s = 1812433253u * (s ^ (s >> 30)) + (unsigned)i + 1u; }
    int pos = 624;
    int K = g_Ktot;
    for (int slot = 0; slot < K; slot++) {
        int M = g_clusM[slot], b = g_clusB[slot], base = g_clusBase[slot];
        if (M <= 1) {
            int gj = b * NPT + g_members[base];
            for (int tt = 0; tt < DS; tt++) g_gidx[slot * DS + tt] = gj;
        } else {
            unsigned int rng = (unsigned int)(M - 1), mask = rng;
            mask |= mask >> 1; mask |= mask >> 2; mask |= mask >> 4; mask |= mask >> 8; mask |= mask >> 16;
            for (int tt = 0; tt < DS; tt++) {
                unsigned int r;
                do {
                    if (pos == 624) {
                        for (int i = 0; i < 624; i++) {
                            unsigned int y = (key[i] & 0x80000000u) | (key[(i + 1) % 624] & 0x7fffffffu);
                            unsigned int v = key[(i + 397) % 624] ^ (y >> 1);
                            key[i] = (y & 1u) ? (v ^ 0x9908b0dfu) : v;
                        }
                        pos = 0;
                    }
                    unsigned int y = key[pos++];
                    y ^= y >> 11; y ^= (y << 7) & 0x9d2c5680u; y ^= (y << 15) & 0xefc60000u; y ^= y >> 18;
                    r = y & mask;
                } while (r > rng);
                g_gidx[slot * DS + tt] = b * NPT + g_members[base + (int)r];
            }
        }
    }
}

// ---- 7: PointNet-lite classifier + BCE ----
__global__ __launch_bounds__(128) void k_classify(const float* __restrict__ pts,
        const float* __restrict__ W1, const float* __restrict__ b1,
        const float* __restrict__ W2, const float* __restrict__ b2,
        const float* __restrict__ W3, const float* __restrict__ b3,
        float* __restrict__ out) {
    __shared__ float sW1[192], sb1[64], sW3[256], sb3[2];
    __shared__ float sp[240];
    __shared__ float sh1[80 * 64];
    __shared__ float sred[128];
    int t = threadIdx.x;
    for (int i = t; i < 192; i += 128) sW1[i] = W1[i];
    if (t < 64) sb1[t] = b1[t];
    for (int i = t; i < 256; i += 128) sW3[i] = W3[i];
    if (t < 2) sb3[t] = b3[t];
    float rW2[64];
#pragma unroll
    for (int k = 0; k < 64; k++) rW2[k] = W2[k * 128 + t];
    float rb2 = b2[t];
    __syncthreads();
    int K = g_Ktot;
    for (int slot = blockIdx.x; slot < K; slot += gridDim.x) {
        for (int i = t; i < 240; i += 128) {
            int pt = i / 3, f = i - pt * 3;
            sp[i] = pts[(size_t)g_gidx[slot * DS + pt] * 3 + f];
        }
        __syncthreads();
        for (int o = t; o < 80 * 64; o += 128) {
            int pt = o >> 6, c = o & 63;
            float a = sb1[c] + sp[pt * 3] * sW1[c] + sp[pt * 3 + 1] * sW1[64 + c] + sp[pt * 3 + 2] * sW1[128 + c];
            sh1[o] = fmaxf(a, 0.f);
        }
        __syncthreads();
        float m = -3.402823466e38f;
        for (int pt = 0; pt < 80; pt++) {
            const float* h = &sh1[pt * 64];
            float a = rb2;
#pragma unroll
            for (int k = 0; k < 64; k++) a = fmaf(h[k], rW2[k], a);
            m = fmaxf(m, a);
        }
        float gt = fmaxf(m, 0.f);
        sred[t] = gt * sW3[2 * t];
        __syncthreads();
        for (int off = 64; off; off >>= 1) { if (t < off) sred[t] += sred[t + off]; __syncthreads(); }
        float l0 = sred[0] + sb3[0];
        __syncthreads();
        sred[t] = gt * sW3[2 * t + 1];
        __syncthreads();
        for (int off = 64; off; off >>= 1) { if (t < off) sred[t] += sred[t + off]; __syncthreads(); }
        if (t == 0) {
            float l1 = sred[0] + sb3[1];
            float loss = fminf(log1pf(expf(l0 - l1)), 100.f);
            atomicAdd(out, loss / (float)g_Kb[g_clusB[slot]]);
        }
        __syncthreads();
    }
}

extern "C" void kernel_launch(void* const* d_in, const int* in_sizes, int n_in,
                              void* d_out, int out_size) {
    const float* feat = (const float*)d_in[0];
    const float* pts  = (const float*)d_in[1];
    const float* W1 = (const float*)d_in[2];
    const float* b1 = (const float*)d_in[3];
    const float* W2 = (const float*)d_in[4];
    const float* b2 = (const float*)d_in[5];
    const float* W3 = (const float*)d_in[6];
    const float* b3 = (const float*)d_in[7];
    float* out = (float*)d_out;
    static int attr_set = 0;
    if (!attr_set) {
        cudaFuncSetAttribute(k_mma, cudaFuncAttributeMaxDynamicSharedMemorySize, SMEM_DYN);
        attr_set = 1;
    }
    k_cvt<<<(NTOT * NF / 2) / 256, 256>>>(feat);
    k_sq<<<NTOT * 32 / 256, 256>>>(feat, out);
    k_mma<<<dim3(NTRI, NB), 256, SMEM_DYN>>>();
    k_rowpq<<<NTOT * 32 / 256, 256>>>();
    k_rcnt<<<64, 256>>>();
    k_rscan<<<1, 32>>>();
    k_assign<<<64, 256>>>();
    for (int it = 0; it < 6; it++) k_jump4<<<NTOT / 256, 256>>>(it & 1);
    k_vfin<<<NTOT / 256, 256>>>();
    k_labfin<<<NTOT / 256, 256>>>();
    k_build<<<1, 1024>>>();
    k_rng<<<1, 1>>>();
    k_classify<<<32, 128>>>(pts, W1, b1, W2, b2, W3, b3, out);
}

// round 8
// speedup vs baseline: 4.0061x; 1.4337x over previous
#include <cuda_runtime.h>
#include <cuda_bf16.h>
#include <cstdint>
#include <math.h>

#define NB 4
#define NPT 4096
#define NF 256
#define NTOT (NB*NPT)
#define DS 80
#define NTILE 32
#define NTRI (NTILE*(NTILE+1)/2)

__device__ uint32_t g_adj32[(size_t)NTOT * 128];
__device__ __nv_bfloat16 g_bf[(size_t)NTOT * NF];
__device__ float g_sq[NTOT];
__device__ int g_p[NTOT], g_q[NTOT], g_root[NTOT], g_labval[NTOT];
__device__ int g_ptrA[NTOT], g_ptrB[NTOT], g_v[NTOT], g_labels[NTOT];
__device__ int g_ccnt[64], g_coff[64];
__device__ int g_hist[NB][NTOT + 1];
__device__ int g_map[NB][NTOT + 1];
__device__ int g_members[NTOT];
__device__ int g_clusM[NTOT], g_clusB[NTOT], g_clusBase[NTOT], g_clusL[NTOT];
__device__ int g_Kb[NB], g_KbBase[NB], g_Ktot, g_Rtot;
__device__ int g_gidx[(size_t)NTOT * DS];

__device__ __forceinline__ uint32_t smem_u32(const void* p) {
    uint32_t a;
    asm("{ .reg .u64 t; cvta.to.shared.u64 t, %1; cvt.u32.u64 %0, t; }" : "=r"(a) : "l"(p));
    return a;
}
__device__ __forceinline__ void cp16(uint32_t dst, const void* src) {
    asm volatile("cp.async.ca.shared.global [%0], [%1], 16;" :: "r"(dst), "l"(src));
}
__device__ __forceinline__ void cp_commit() { asm volatile("cp.async.commit_group;"); }
__device__ __forceinline__ void cp_wait1() { asm volatile("cp.async.wait_group 1;"); }
__device__ __forceinline__ void cp_wait0() { asm volatile("cp.async.wait_group 0;"); }
__device__ __forceinline__ void ldsm4(uint32_t* r, uint32_t a) {
    asm volatile("ldmatrix.sync.aligned.m8n8.x4.shared.b16 {%0,%1,%2,%3}, [%4];"
        : "=r"(r[0]), "=r"(r[1]), "=r"(r[2]), "=r"(r[3]) : "r"(a));
}
__device__ __forceinline__ void ldsm2(uint32_t* r, uint32_t a) {
    asm volatile("ldmatrix.sync.aligned.m8n8.x2.shared.b16 {%0,%1}, [%2];"
        : "=r"(r[0]), "=r"(r[1]) : "r"(a));
}
__device__ __forceinline__ void mma16816(float* c, const uint32_t* a, const uint32_t* b) {
    asm volatile("mma.sync.aligned.m16n8k16.row.col.f32.bf16.bf16.f32 "
        "{%0,%1,%2,%3},{%4,%5,%6,%7},{%8,%9},{%0,%1,%2,%3};"
        : "+f"(c[0]), "+f"(c[1]), "+f"(c[2]), "+f"(c[3])
        : "r"(a[0]), "r"(a[1]), "r"(a[2]), "r"(a[3]), "r"(b[0]), "r"(b[1]));
}

#define STR 80        /* smem row stride bytes (32 bf16 data + pad) */
#define STG 20480     /* bytes per stage: A + B, each 128 x 80 */
#define T_A 0
#define T_B 10240
#define OFF_SQJ 40960
#define SMEM_DYN 41472
#define ST_N 0
#define ST_T 16896

// ---- 1: fused fp32->bf16 convert + row sum of squares (+ zero output) ----
__global__ void k_cvtsq(const float* __restrict__ feat, float* __restrict__ out) {
    int gt = blockIdx.x * blockDim.x + threadIdx.x;
    if (gt == 0) out[0] = 0.f;
    int w = gt >> 5, lane = gt & 31;
    const float* r = feat + (size_t)w * NF;
    __nv_bfloat16* d = g_bf + (size_t)w * NF;
    float s = 0.f;
#pragma unroll
    for (int t = 0; t < NF / 32; t++) {
        float x = r[t * 32 + lane];
        s = fmaf(x, x, s);
        d[t * 32 + lane] = __float2bfloat16_rn(x);
    }
#pragma unroll
    for (int o = 16; o; o >>= 1) s += __shfl_xor_sync(0xffffffffu, s, o);
    if (lane == 0) g_sq[w] = s;
}

// ---- 2: bf16 HMMA GEMM, cp.async double-buffered, 2 CTA/SM -> packed adjacency ----
__global__ __launch_bounds__(256, 2) void k_mma() {
    extern __shared__ char sb[];
    uint32_t s0 = smem_u32(sb);
    int t = threadIdx.x, wid = t >> 5, l = t & 31;
    int wm = wid >> 2, wn = wid & 3;
    int ti = blockIdx.x, bi = 0;
    while (ti >= NTILE - bi) { ti -= NTILE - bi; bi++; }
    int bj = bi + ti;
    int b = blockIdx.y;
    int iBase = bi * 128, jBase = bj * 128;
    bool diag = (bi == bj);

    if (t < 128) ((float*)(sb + OFF_SQJ))[t] = g_sq[b * NPT + jBase + t];

    const __nv_bfloat16* A = g_bf + (size_t)(b * NPT + iBase) * NF;
    const __nv_bfloat16* B = g_bf + (size_t)(b * NPT + jBase) * NF;

    float acc[4][4][4];
#pragma unroll
    for (int mt = 0; mt < 4; mt++)
#pragma unroll
        for (int nt = 0; nt < 4; nt++)
#pragma unroll
            for (int r = 0; r < 4; r++) acc[mt][nt][r] = 0.f;

    int row = t >> 1, half = t & 1;
    uint32_t dce = s0 + row * STR + half * 32;
    size_t gce = (size_t)row * NF + half * 16;

    // prologue: chunk 0 -> stage 0
    {
        cp16(dce + T_A, A + gce); cp16(dce + T_A + 16, A + gce + 8);
        cp16(dce + T_B, B + gce); cp16(dce + T_B + 16, B + gce + 8);
        cp_commit();
    }
#pragma unroll 1
    for (int c = 0; c < 8; c++) {
        __syncthreads();
        if (c < 7) {
            uint32_t d = dce + ((c + 1) & 1) * STG;
            size_t g2 = gce + (size_t)(c + 1) * 32;
            cp16(d + T_A, A + g2); cp16(d + T_A + 16, A + g2 + 8);
            cp16(d + T_B, B + g2); cp16(d + T_B + 16, B + g2 + 8);
            cp_commit();
            cp_wait1();
        } else {
            cp_wait0();
        }
        __syncthreads();
        uint32_t stg = s0 + (c & 1) * STG;
#pragma unroll
        for (int kk = 0; kk < 2; kk++) {
            uint32_t af[4][4], bfr[4][2];
#pragma unroll
            for (int mt = 0; mt < 4; mt++)
                ldsm4(af[mt], stg + T_A + (wm * 64 + mt * 16 + (l & 15)) * STR + kk * 32 + (l >> 4) * 16);
#pragma unroll
            for (int nt = 0; nt < 4; nt++)
                ldsm2(bfr[nt], stg + T_B + (wn * 32 + nt * 8 + (l & 7)) * STR + kk * 32 + ((l >> 3) & 1) * 16);
#pragma unroll
            for (int mt = 0; mt < 4; mt++)
#pragma unroll
                for (int nt = 0; nt < 4; nt++)
                    mma16816(acc[mt][nt], af[mt], bfr[nt]);
        }
    }
    __syncthreads();

    // epilogue: threshold -> byte staging (normal + transposed)
    int g = l >> 2, tg = l & 3;
    float sqia[8];
#pragma unroll
    for (int mt = 0; mt < 4; mt++)
#pragma unroll
        for (int h = 0; h < 2; h++)
            sqia[mt * 2 + h] = g_sq[b * NPT + iBase + wm * 64 + mt * 16 + g + h * 8];
    const float* sqj = (const float*)(sb + OFF_SQJ);
#pragma unroll
    for (int mt = 0; mt < 4; mt++)
#pragma unroll
        for (int nt = 0; nt < 4; nt++)
#pragma unroll
            for (int r = 0; r < 4; r++) {
                int ro = wm * 64 + mt * 16 + g + (r >> 1) * 8;
                int co = wn * 32 + nt * 8 + tg * 2 + (r & 1);
                float d2 = sqia[mt * 2 + (r >> 1)] + sqj[co] - 2.f * acc[mt][nt][r];
                unsigned char bit = (sqrtf(fmaxf(d2, 0.f)) < 22.63f) ? 1 : 0;
                ((unsigned char*)sb)[ST_N + ro * 132 + co] = bit;
                if (!diag) ((unsigned char*)sb)[ST_T + co * 132 + ro] = bit;
            }
    __syncthreads();
    for (int idx = t; idx < 512; idx += 256) {
        int r = idx >> 2, wc = idx & 3;
        const uint32_t* src = (const uint32_t*)(sb + ST_N + r * 132 + wc * 32);
        uint32_t bits = 0;
#pragma unroll
        for (int i = 0; i < 8; i++) {
            uint32_t u = src[i];
            bits |= ((u & 1) | ((u >> 7) & 2) | ((u >> 14) & 4) | ((u >> 21) & 8)) << (4 * i);
        }
        g_adj32[(size_t)(b * NPT + iBase + r) * 128 + (jBase >> 5) + wc] = bits;
    }
    if (!diag) {
        for (int idx = t; idx < 512; idx += 256) {
            int r = idx >> 2, wc = idx & 3;
            const uint32_t* src = (const uint32_t*)(sb + ST_T + r * 132 + wc * 32);
            uint32_t bits = 0;
#pragma unroll
            for (int i = 0; i < 8; i++) {
                uint32_t u = src[i];
                bits |= ((u & 1) | ((u >> 7) & 2) | ((u >> 14) & 4) | ((u >> 21) & 8)) << (4 * i);
            }
            g_adj32[(size_t)(b * NPT + jBase + r) * 128 + (iBase >> 5) + wc] = bits;
        }
    }
}

// ---- 3: per-row p (last neighbor < j) and q (last neighbor) over bit rows ----
__global__ void k_rowpq() {
    int gw = (blockIdx.x * blockDim.x + threadIdx.x) >> 5;
    int lane = threadIdx.x & 31;
    int j = gw & (NPT - 1);
    const uint4* rp = (const uint4*)(g_adj32 + (size_t)gw * 128);
    uint4 v = rp[lane];
    uint32_t ws[4] = {v.x, v.y, v.z, v.w};
    int pmax = -1, qmax = -1;
    int jw = j >> 5, jb = j & 31;
#pragma unroll
    for (int k = 0; k < 4; k++) {
        int wi = lane * 4 + k;
        uint32_t w = ws[k];
        if (w) qmax = max(qmax, wi * 32 + 31 - __clz(w));
        uint32_t mp = (wi < jw) ? w : ((wi == jw && jb) ? (w & ((1u << jb) - 1)) : 0u);
        if (mp) pmax = max(pmax, wi * 32 + 31 - __clz(mp));
    }
#pragma unroll
    for (int o = 16; o; o >>= 1) {
        qmax = max(qmax, __shfl_xor_sync(0xffffffffu, qmax, o));
        pmax = max(pmax, __shfl_xor_sync(0xffffffffu, pmax, o));
    }
    if (lane == 0) { g_p[gw] = pmax; g_q[gw] = qmax; g_root[gw] = (pmax < 0); }
}

// ---- 4: root counting / scan / assignment / 8-hop pointer jumping ----
__global__ void k_rcnt() {
    __shared__ int wsum[8];
    int t = threadIdx.x;
    int x = blockIdx.x * 256 + t;
    int r = g_root[x];
#pragma unroll
    for (int o = 16; o; o >>= 1) r += __shfl_xor_sync(0xffffffffu, r, o);
    if ((t & 31) == 0) wsum[t >> 5] = r;
    __syncthreads();
    if (t == 0) {
        int s = 0;
        for (int w = 0; w < 8; w++) s += wsum[w];
        g_ccnt[blockIdx.x] = s;
    }
}
__global__ void k_rscan() {
    if (threadIdx.x == 0) {
        int s = 0;
        for (int i = 0; i < 64; i++) { g_coff[i] = s; s += g_ccnt[i]; }
        g_Rtot = s;
    }
}
__global__ void k_assign() {
    __shared__ int woff[8];
    int t = threadIdx.x, lane = t & 31, wid = t >> 5;
    int x = blockIdx.x * 256 + t;
    int isr = g_root[x];
    unsigned int bal = __ballot_sync(0xffffffffu, isr);
    int lp = __popc(bal & ((1u << lane) - 1));
    if (lane == 0) woff[wid] = __popc(bal);
    __syncthreads();
    if (t == 0) {
        int s = 0;
        for (int w = 0; w < 8; w++) { int c = woff[w]; woff[w] = s; s += c; }
    }
    __syncthreads();
    if (isr) { g_labval[x] = 1 + g_coff[blockIdx.x] + woff[wid] + lp; g_ptrA[x] = x; }
    else { g_labval[x] = 0; g_ptrA[x] = (x & ~(NPT - 1)) + g_p[x]; }
}
__global__ void k_jump8(int phase) {
    int x = blockIdx.x * blockDim.x + threadIdx.x;
    if (phase == 0) {
        int a = g_ptrA[x];
#pragma unroll
        for (int h = 0; h < 7; h++) a = g_ptrA[a];
        g_ptrB[x] = a;
    } else {
        int a = g_ptrB[x];
#pragma unroll
        for (int h = 0; h < 7; h++) a = g_ptrB[a];
        g_ptrA[x] = a;
    }
}
__global__ void k_vfin() {
    int x = blockIdx.x * blockDim.x + threadIdx.x;
    g_v[x] = g_labval[g_ptrA[x]];
}
__global__ void k_labfin() {
    int x = blockIdx.x * blockDim.x + threadIdx.x;
    g_labels[x] = g_v[(x & ~(NPT - 1)) + g_q[x]];
}

// ---- 5: histogram / unique / stable member compaction ----
__global__ __launch_bounds__(1024) void k_build() {
    __shared__ int wcnt[32], wpre[32], sTot, sWritten;
    int t = threadIdx.x, lane = t & 31, wid = t >> 5;
    for (int i = t; i < NB * (NTOT + 1); i += 1024) (&g_hist[0][0])[i] = 0;
    __syncthreads();
#pragma unroll
    for (int e = 0; e < 16; e++) {
        int x = t * 16 + e;
        atomicAdd(&g_hist[x >> 12][g_labels[x]], 1);
    }
    __syncthreads();
    int R = g_Rtot;
    if (t < NB) {
        int k = 0;
        for (int l = 1; l <= R; l++) if (g_hist[t][l] > 0) { g_map[t][l] = k; k++; }
        g_Kb[t] = k;
    }
    __syncthreads();
    if (t == 0) {
        int s = 0;
        for (int b = 0; b < NB; b++) { g_KbBase[b] = s; s += g_Kb[b]; }
        g_Ktot = s;
    }
    __syncthreads();
    if (t < NB) {
        int b = t, off = 0, k = 0;
        for (int l = 1; l <= R; l++) {
            int c = g_hist[b][l];
            if (c > 0) {
                int slot = g_KbBase[b] + k;
                g_clusM[slot] = c; g_clusB[slot] = b;
                g_clusBase[slot] = b * NPT + off; g_clusL[slot] = l;
                off += c; k++;
            }
        }
    }
    __syncthreads();
    int K = g_Ktot;
    for (int slot = 0; slot < K; slot++) {
        int b = g_clusB[slot], l = g_clusL[slot], base = g_clusBase[slot];
        if (t == 0) sWritten = 0;
        __syncthreads();
        for (int chunk = 0; chunk < NPT; chunk += 1024) {
            int j = chunk + t;
            bool m = (g_labels[b * NPT + j] == l);
            unsigned int bal = __ballot_sync(0xffffffffu, m);
            int lp = __popc(bal & ((1u << lane) - 1));
            if (lane == 0) wcnt[wid] = __popc(bal);
            __syncthreads();
            if (t == 0) {
                int s = 0;
                for (int w = 0; w < 32; w++) { wpre[w] = s; s += wcnt[w]; }
                sTot = s;
            }
            __syncthreads();
            if (m) g_members[base + sWritten + wpre[wid] + lp] = j;
            __syncthreads();
            if (t == 0) sWritten += sTot;
            __syncthreads();
        }
    }
}

// ---- 6: numpy RandomState(0).choice replay ----
__global__ void k_rng() {
    unsigned int key[624];
    unsigned int s = 0u;
    for (int i = 0; i < 624; i++) { key[i] = s; s = 1812433253u * (s ^ (s >> 30)) + (unsigned)i + 1u; }
    int pos = 624;
    int K = g_Ktot;
    for (int slot = 0; slot < K; slot++) {
        int M = g_clusM[slot], b = g_clusB[slot], base = g_clusBase[slot];
        if (M <= 1) {
            int gj = b * NPT + g_members[base];
            for (int tt = 0; tt < DS; tt++) g_gidx[slot * DS + tt] = gj;
        } else {
            unsigned int rng = (unsigned int)(M - 1), mask = rng;
            mask |= mask >> 1; mask |= mask >> 2; mask |= mask >> 4; mask |= mask >> 8; mask |= mask >> 16;
            for (int tt = 0; tt < DS; tt++) {
                unsigned int r;
                do {
                    if (pos == 624) {
                        for (int i = 0; i < 624; i++) {
                            unsigned int y = (key[i] & 0x80000000u) | (key[(i + 1) % 624] & 0x7fffffffu);
                            unsigned int v = key[(i + 397) % 624] ^ (y >> 1);
                            key[i] = (y & 1u) ? (v ^ 0x9908b0dfu) : v;
                        }
                        pos = 0;
                    }
                    unsigned int y = key[pos++];
                    y ^= y >> 11; y ^= (y << 7) & 0x9d2c5680u; y ^= (y << 15) & 0xefc60000u; y ^= y >> 18;
                    r = y & mask;
                } while (r > rng);
                g_gidx[slot * DS + tt] = b * NPT + g_members[base + (int)r];
            }
        }
    }
}

// ---- 7: PointNet-lite classifier + BCE ----
__global__ __launch_bounds__(128) void k_classify(const float* __restrict__ pts,
        const float* __restrict__ W1, const float* __restrict__ b1,
        const float* __restrict__ W2, const float* __restrict__ b2,
        const float* __restrict__ W3, const float* __restrict__ b3,
        float* __restrict__ out) {
    __shared__ float sW1[192], sb1[64], sW3[256], sb3[2];
    __shared__ float sp[240];
    __shared__ float sh1[80 * 64];
    __shared__ float sred[128];
    int t = threadIdx.x;
    for (int i = t; i < 192; i += 128) sW1[i] = W1[i];
    if (t < 64) sb1[t] = b1[t];
    for (int i = t; i < 256; i += 128) sW3[i] = W3[i];
    if (t < 2) sb3[t] = b3[t];
    float rW2[64];
#pragma unroll
    for (int k = 0; k < 64; k++) rW2[k] = W2[k * 128 + t];
    float rb2 = b2[t];
    __syncthreads();
    int K = g_Ktot;
    for (int slot = blockIdx.x; slot < K; slot += gridDim.x) {
        for (int i = t; i < 240; i += 128) {
            int pt = i / 3, f = i - pt * 3;
            sp[i] = pts[(size_t)g_gidx[slot * DS + pt] * 3 + f];
        }
        __syncthreads();
        for (int o = t; o < 80 * 64; o += 128) {
            int pt = o >> 6, c = o & 63;
            float a = sb1[c] + sp[pt * 3] * sW1[c] + sp[pt * 3 + 1] * sW1[64 + c] + sp[pt * 3 + 2] * sW1[128 + c];
            sh1[o] = fmaxf(a, 0.f);
        }
        __syncthreads();
        float m = -3.402823466e38f;
        for (int pt = 0; pt < 80; pt++) {
            const float* h = &sh1[pt * 64];
            float a = rb2;
#pragma unroll
            for (int k = 0; k < 64; k++) a = fmaf(h[k], rW2[k], a);
            m = fmaxf(m, a);
        }
        float gt = fmaxf(m, 0.f);
        sred[t] = gt * sW3[2 * t];
        __syncthreads();
        for (int off = 64; off; off >>= 1) { if (t < off) sred[t] += sred[t + off]; __syncthreads(); }
        float l0 = sred[0] + sb3[0];
        __syncthreads();
        sred[t] = gt * sW3[2 * t + 1];
        __syncthreads();
        for (int off = 64; off; off >>= 1) { if (t < off) sred[t] += sred[t + off]; __syncthreads(); }
        if (t == 0) {
            float l1 = sred[0] + sb3[1];
            float loss = fminf(log1pf(expf(l0 - l1)), 100.f);
            atomicAdd(out, loss / (float)g_Kb[g_clusB[slot]]);
        }
        __syncthreads();
    }
}

extern "C" void kernel_launch(void* const* d_in, const int* in_sizes, int n_in,
                              void* d_out, int out_size) {
    const float* feat = (const float*)d_in[0];
    const float* pts  = (const float*)d_in[1];
    const float* W1 = (const float*)d_in[2];
    const float* b1 = (const float*)d_in[3];
    const float* W2 = (const float*)d_in[4];
    const float* b2 = (const float*)d_in[5];
    const float* W3 = (const float*)d_in[6];
    const float* b3 = (const float*)d_in[7];
    float* out = (float*)d_out;
    k_cvtsq<<<NTOT * 32 / 256, 256>>>(feat, out);
    k_mma<<<dim3(NTRI, NB), 256, SMEM_DYN>>>();
    k_rowpq<<<NTOT * 32 / 256, 256>>>();
    k_rcnt<<<64, 256>>>();
    k_rscan<<<1, 32>>>();
    k_assign<<<64, 256>>>();
    for (int it = 0; it < 4; it++) k_jump8<<<NTOT / 256, 256>>>(it & 1);
    k_vfin<<<NTOT / 256, 256>>>();
    k_labfin<<<NTOT / 256, 256>>>();
    k_build<<<1, 1024>>>();
    k_rng<<<1, 1>>>();
    k_classify<<<32, 128>>>(pts, W1, b1, W2, b2, W3, b3, out);
}